// round 10
// baseline (speedup 1.0000x reference)
#include <cuda_runtime.h>
#include <cuda_fp16.h>
#include <cstdint>

// Problem constants
#define T_TOK 4096      // total tokens (B*S)
#define DDIM  4096      // D_IN == D_OUT
#define NE    8         // experts

// GEMM tile config: CTA tile 128x128, 8 warps (2x4), warp tile 64x32, fp16 operands
#define BM 128
#define BN 128
#define BK 64           // halves per k-tile
#define NSTAGE 3
#define ALD_H 72        // halves per smem row (64 + 8 pad) -> conflict-free
#define GEMM_THREADS 256

// -------- device-global scratch (no allocation allowed) --------
__device__ int    g_cnt[NE];
__device__ float  g_importance[NE];
__device__ int    g_tok[NE * T_TOK];
__device__ float  g_scale[NE * T_TOK];
__device__ __half g_xh[(size_t)T_TOK * DDIM];        // 32 MB  fp16 x
__device__ __half g_wh[(size_t)NE * DDIM * DDIM];    // 256 MB fp16 W

// ---------------------------------------------------------------
__global__ void reset_kernel() {
    int i = threadIdx.x;
    if (i < NE) { g_cnt[i] = 0; g_importance[i] = 0.f; }
}

// One block (128 threads) per token: logits = tanh(x @ gw1^T) @ gw2^T, top-2,
// softmax, append to per-expert lists. Also writes fp16 x to g_xh.
__global__ void gate_kernel(const float4* __restrict__ x4,
                            const float4* __restrict__ gw1_4,
                            const float* __restrict__ gw2) {
    int t = blockIdx.x;
    const float4* xr = x4 + (size_t)t * (DDIM / 4);
    uint2* xc = (uint2*)(g_xh + (size_t)t * DDIM);

    float acc[NE];
#pragma unroll
    for (int e = 0; e < NE; e++) acc[e] = 0.f;

    for (int i = threadIdx.x; i < DDIM / 4; i += 128) {
        float4 v = xr[i];
        __half2 h0 = __floats2half2_rn(v.x, v.y);
        __half2 h1 = __floats2half2_rn(v.z, v.w);
        uint2 pk;
        pk.x = *(uint32_t*)&h0;
        pk.y = *(uint32_t*)&h1;
        xc[i] = pk;
#pragma unroll
        for (int e = 0; e < NE; e++) {
            float4 w = gw1_4[e * (DDIM / 4) + i];
            acc[e] += v.x * w.x + v.y * w.y + v.z * w.z + v.w * w.w;
        }
    }
#pragma unroll
    for (int e = 0; e < NE; e++) {
#pragma unroll
        for (int o = 16; o > 0; o >>= 1)
            acc[e] += __shfl_xor_sync(0xffffffffu, acc[e], o);
    }
    __shared__ float part[NE][4];
    __shared__ float hs[NE];
    __shared__ float ls[NE];
    int lane = threadIdx.x & 31, warp = threadIdx.x >> 5;
    if (lane == 0) {
#pragma unroll
        for (int e = 0; e < NE; e++) part[e][warp] = acc[e];
    }
    __syncthreads();
    if (threadIdx.x < NE) {
        int e = threadIdx.x;
        hs[e] = tanhf(part[e][0] + part[e][1] + part[e][2] + part[e][3]);
    }
    __syncthreads();
    if (threadIdx.x < NE) {
        int j = threadIdx.x;
        float l = 0.f;
#pragma unroll
        for (int e = 0; e < NE; e++) l += gw2[j * NE + e] * hs[e];
        ls[j] = l;
    }
    __syncthreads();
    if (threadIdx.x == 0) {
        int i0 = 0; float v0 = ls[0];
        for (int j = 1; j < NE; j++) if (ls[j] > v0) { v0 = ls[j]; i0 = j; }
        int i1 = -1; float v1 = -3.4e38f;
        for (int j = 0; j < NE; j++) if (j != i0 && ls[j] > v1) { v1 = ls[j]; i1 = j; }
        float z  = expf(v1 - v0);
        float s0 = 1.f / (1.f + z);
        float s1 = z * s0;
        int p0 = atomicAdd(&g_cnt[i0], 1);
        g_tok[i0 * T_TOK + p0]   = t;
        g_scale[i0 * T_TOK + p0] = s0;
        int p1 = atomicAdd(&g_cnt[i1], 1);
        g_tok[i1 * T_TOK + p1]   = t;
        g_scale[i1 * T_TOK + p1] = s1;
        atomicAdd(&g_importance[i0], s0);
        atomicAdd(&g_importance[i1], s1);
    }
}

__global__ void loss_kernel(float* __restrict__ out) {
    float v[NE], w[NE];
    float m1 = 0.f, m2 = 0.f;
#pragma unroll
    for (int e = 0; e < NE; e++) {
        v[e] = g_importance[e];
        w[e] = (float)g_cnt[e];
        m1 += v[e]; m2 += w[e];
    }
    m1 *= (1.f / NE); m2 *= (1.f / NE);
    float var1 = 0.f, var2 = 0.f;
#pragma unroll
    for (int e = 0; e < NE; e++) {
        float d1 = v[e] - m1; var1 += d1 * d1;
        float d2 = w[e] - m2; var2 += d2 * d2;
    }
    var1 *= (1.f / (NE - 1)); var2 *= (1.f / (NE - 1));
    out[0] = 0.01f * (var1 / (m1 * m1 + 1e-10f) + var2 / (m2 * m2 + 1e-10f));
}

// ---------------- W pre-convert (fp32 -> fp16 rn) ----------------
__global__ void cvt_w_kernel(const float4* __restrict__ src) {
    int i = blockIdx.x * 256 + threadIdx.x;
    const int n4 = (int)((size_t)NE * DDIM * (DDIM / 4));
    if (i < n4) {
        float4 v = src[i];
        __half2 h0 = __floats2half2_rn(v.x, v.y);
        __half2 h1 = __floats2half2_rn(v.z, v.w);
        uint2 pk;
        pk.x = *(uint32_t*)&h0;
        pk.y = *(uint32_t*)&h1;
        ((uint2*)g_wh)[i] = pk;
    }
}

// ---------------------------------------------------------------
__device__ __forceinline__ void mma_f16(float* c, const uint32_t* a, const uint32_t* b) {
    asm volatile(
        "mma.sync.aligned.m16n8k16.row.col.f32.f16.f16.f32 "
        "{%0,%1,%2,%3}, {%4,%5,%6,%7}, {%8,%9}, {%0,%1,%2,%3};\n"
        : "+f"(c[0]), "+f"(c[1]), "+f"(c[2]), "+f"(c[3])
        : "r"(a[0]), "r"(a[1]), "r"(a[2]), "r"(a[3]), "r"(b[0]), "r"(b[1]));
}
__device__ __forceinline__ void ldm_x4(uint32_t& r0, uint32_t& r1, uint32_t& r2, uint32_t& r3,
                                       uint32_t saddr) {
    asm volatile("ldmatrix.sync.aligned.m8n8.x4.shared.b16 {%0,%1,%2,%3}, [%4];\n"
                 : "=r"(r0), "=r"(r1), "=r"(r2), "=r"(r3) : "r"(saddr));
}
__device__ __forceinline__ void cp_async16(uint32_t saddr, const void* gsrc) {
    asm volatile("cp.async.cg.shared.global [%0], [%1], 16;\n" :: "r"(saddr), "l"(gsrc) : "memory");
}

// Grouped expert GEMM on fp16 operands (fp32 accumulate); epilogue scatter-add.
// CTA tile 128x128, 8 warps (2 along M x 4 along N), warp tile 64x32.
// 2 CTAs/SM -> 16 warps/SM for MMA latency cover. BK=64, 3-stage cp.async.
__global__ void __launch_bounds__(GEMM_THREADS, 2)
moe_gemm(const float* __restrict__ bias, float* __restrict__ y) {
    int e   = blockIdx.z;
    int cnt = g_cnt[e];
    int m0  = blockIdx.x * BM;
    if (m0 >= cnt) return;
    int n0  = blockIdx.y * BN;

    extern __shared__ __half smh[];
    __half* Ash   = smh;                                   // NSTAGE*BM*ALD_H halves
    __half* Bsh   = Ash + NSTAGE * BM * ALD_H;             // NSTAGE*BN*ALD_H halves
    float* sBias  = (float*)(Bsh + NSTAGE * BN * ALD_H);   // BN
    float* sScale = sBias + BN;                            // BM
    int*   sTok   = (int*)(sScale + BM);                   // BM

    uint32_t sb = (uint32_t)__cvta_generic_to_shared(smh);
    uint32_t aStage0 = sb;
    uint32_t bStage0 = sb + NSTAGE * BM * ALD_H * 2;

    int tid = threadIdx.x;
    if (tid < BM) {
        int m = m0 + tid;
        bool valid = m < cnt;
        sTok[tid]   = valid ? g_tok[e * T_TOK + m]   : 0;
        sScale[tid] = valid ? g_scale[e * T_TOK + m] : 0.f;
    } else {
        int n = tid - BM;
        sBias[n] = bias[e * DDIM + n0 + n];
    }
    __syncthreads();

    // cp.async slots: 256 threads cover 32 rows x 8 chunk-cols (16B=8 halves); 4 row-passes.
    int r_ld = tid >> 3, c_ld = tid & 7;     // r_ld 0..31, c_ld 0..7
    const __half* a_src[4];
#pragma unroll
    for (int it = 0; it < 4; it++) {
        int r = r_ld + it * 32;
        a_src[it] = g_xh + (size_t)sTok[r] * DDIM + c_ld * 8;
    }
    const __half* b_base = g_wh + ((size_t)e * DDIM + n0 + r_ld) * DDIM + c_ld * 8;
    uint32_t stDstA = aStage0 + (r_ld * ALD_H + c_ld * 8) * 2;
    uint32_t stDstB = bStage0 + (r_ld * ALD_H + c_ld * 8) * 2;

    auto load_stage = [&](int stage, int kt) {
        int kk = kt * BK;
        uint32_t so = (uint32_t)(stage * (BM * ALD_H * 2));
#pragma unroll
        for (int it = 0; it < 4; it++) {
            cp_async16(stDstA + so + it * (32 * ALD_H * 2), a_src[it] + kk);
        }
#pragma unroll
        for (int it = 0; it < 4; it++) {
            cp_async16(stDstB + so + it * (32 * ALD_H * 2),
                       b_base + (size_t)(it * 32) * DDIM + kk);
        }
        asm volatile("cp.async.commit_group;\n" ::: "memory");
    };

    const int KT = DDIM / BK;  // 64
    load_stage(0, 0);
    load_stage(1, 1);

    int warp = tid >> 5;        // 0..7
    int wm   = warp & 1;        // 2 warps along M -> 64 rows each
    int wn   = warp >> 1;       // 4 warps along N -> 32 cols each
    int lane = tid & 31;
    int gid  = lane >> 2;       // 0..7
    int tg   = lane & 3;        // 0..3

    // ldmatrix per-thread address components (halves)
    int rA = ((lane >> 3) & 1) * 8 + (lane & 7);   // row within 16-row A tile
    int cA = ((lane >> 4) & 1) * 8;                // k-chunk within k16
    int rB = ((lane >> 4) & 1) * 8 + (lane & 7);   // row within 16-row B (n) tile
    int cB = ((lane >> 3) & 1) * 8;

    float c[4][4][4];
#pragma unroll
    for (int mi = 0; mi < 4; mi++)
#pragma unroll
        for (int ni = 0; ni < 4; ni++)
#pragma unroll
            for (int j = 0; j < 4; j++) c[mi][ni][j] = 0.f;

    for (int i = 0; i < KT; i++) {
        if (i < KT - 1) {
            asm volatile("cp.async.wait_group 1;\n" ::: "memory");
        } else {
            asm volatile("cp.async.wait_group 0;\n" ::: "memory");
        }
        __syncthreads();
        if (i + 2 < KT) load_stage((i + 2) % NSTAGE, i + 2);

        uint32_t aBase = aStage0 + (i % NSTAGE) * (BM * ALD_H * 2)
                       + ((wm * 64 + rA) * ALD_H + cA) * 2;
        uint32_t bBase = bStage0 + (i % NSTAGE) * (BN * ALD_H * 2)
                       + ((wn * 32 + rB) * ALD_H + cB) * 2;

#pragma unroll
        for (int ks = 0; ks < BK / 16; ks++) {           // 4 k16 steps
            uint32_t a[4][4], b[4][2];
#pragma unroll
            for (int mi = 0; mi < 4; mi++) {
                ldm_x4(a[mi][0], a[mi][1], a[mi][2], a[mi][3],
                       aBase + (mi * 16 * ALD_H + ks * 16) * 2);
            }
#pragma unroll
            for (int p = 0; p < 2; p++) {                // ni pairs
                ldm_x4(b[2 * p][0], b[2 * p][1], b[2 * p + 1][0], b[2 * p + 1][1],
                       bBase + (p * 16 * ALD_H + ks * 16) * 2);
            }
#pragma unroll
            for (int mi = 0; mi < 4; mi++)
#pragma unroll
                for (int ni = 0; ni < 4; ni++)
                    mma_f16(c[mi][ni], a[mi], b[ni]);
        }
    }

    // epilogue: scatter-add
#pragma unroll
    for (int mi = 0; mi < 4; mi++) {
#pragma unroll
        for (int half = 0; half < 2; half++) {
            int r = wm * 64 + mi * 16 + gid + half * 8;
            if (m0 + r >= cnt) continue;
            int   tok = sTok[r];
            float sc  = sScale[r];
            float* yr = y + (size_t)tok * DDIM + n0;
#pragma unroll
            for (int ni = 0; ni < 4; ni++) {
                int col = wn * 32 + ni * 8 + tg * 2;
                float v0 = sc * (c[mi][ni][half * 2 + 0] + sBias[col]);
                float v1 = sc * (c[mi][ni][half * 2 + 1] + sBias[col + 1]);
                atomicAdd(&yr[col],     v0);
                atomicAdd(&yr[col + 1], v1);
            }
        }
    }
}

// ---------------------------------------------------------------
extern "C" void kernel_launch(void* const* d_in, const int* in_sizes, int n_in,
                              void* d_out, int out_size) {
    const float* x   = (const float*)d_in[0];
    const float* gw1 = (const float*)d_in[1];
    const float* gw2 = (const float*)d_in[2];
    const float* ew  = (const float*)d_in[3];
    const float* eb  = (const float*)d_in[4];
    float* out = (float*)d_out;

    // Launch order arranged so moe_gemm is the 5th kernel launch (ncu -s 5 -c 1
    // captures it): memset(1), reset(2), cvt_w(3), gate(4), moe_gemm(5), loss(6).
    cudaMemsetAsync(out, 0, (size_t)out_size * sizeof(float));

    reset_kernel<<<1, 32>>>();

    {
        int n4w = (int)((size_t)NE * DDIM * (DDIM / 4));
        cvt_w_kernel<<<(n4w + 255) / 256, 256>>>((const float4*)ew);
    }

    gate_kernel<<<T_TOK, 128>>>((const float4*)x, (const float4*)gw1, gw2);

    int smem_bytes = (NSTAGE * (BM * ALD_H + BN * ALD_H)) * 2 + (BN + BM + BM) * 4;
    cudaFuncSetAttribute(moe_gemm, cudaFuncAttributeMaxDynamicSharedMemorySize, smem_bytes);
    moe_gemm<<<dim3(T_TOK / BM, DDIM / BN, NE), GEMM_THREADS, smem_bytes>>>(eb, out);

    if (out_size > T_TOK * DDIM) {
        loss_kernel<<<1, 1>>>(out + (size_t)T_TOK * DDIM);
    }
}

// round 11
// speedup vs baseline: 1.4604x; 1.4604x over previous
#include <cuda_runtime.h>
#include <cuda_fp16.h>
#include <cstdint>

// Problem constants
#define T_TOK 4096      // total tokens (B*S)
#define DDIM  4096      // D_IN == D_OUT
#define NE    8         // experts

// GEMM tile config: CTA tile 128x128, 4 warps (2x2), warp tile 64x64, fp16 operands
#define BM 128
#define BN 128
#define BK 64           // halves per k-tile
#define NSTAGE 3
#define ALD_H 72        // halves per smem row (64 + 8 pad) -> conflict-free
#define GEMM_THREADS 128

// prep kernel split
#define CVT_BLOCKS 8192          // W-convert blocks (256 thr, 16 float4 each)
#define PREP_BLOCKS (CVT_BLOCKS + T_TOK)

// -------- device-global scratch (no allocation allowed) --------
__device__ int    g_cnt[NE];
__device__ float  g_importance[NE];
__device__ int    g_tok[NE * T_TOK];
__device__ float  g_scale[NE * T_TOK];
__device__ __half g_xh[(size_t)T_TOK * DDIM];        // 32 MB  fp16 x
__device__ __half g_wh[(size_t)NE * DDIM * DDIM];    // 256 MB fp16 W

// ---------------------------------------------------------------
__global__ void reset_kernel() {
    int i = threadIdx.x;
    if (i < NE) { g_cnt[i] = 0; g_importance[i] = 0.f; }
}

// Fused prep kernel (256 threads):
//   blockIdx < CVT_BLOCKS              : convert a contiguous chunk of W to fp16
//   blockIdx in [CVT_BLOCKS, +T_TOK)   : gate for one token + fp16 x write
__global__ void prep_kernel(const float4* __restrict__ x4,
                            const float4* __restrict__ gw1_4,
                            const float* __restrict__ gw2,
                            const float4* __restrict__ ew4) {
    if (blockIdx.x < CVT_BLOCKS) {
        // ---- W convert: 256 thr x 16 float4 = 4096 float4 per block ----
        int base = blockIdx.x * 4096 + threadIdx.x;
#pragma unroll
        for (int it = 0; it < 16; it++) {
            int i = base + it * 256;
            float4 v = ew4[i];
            __half2 h0 = __floats2half2_rn(v.x, v.y);
            __half2 h1 = __floats2half2_rn(v.z, v.w);
            uint2 pk;
            pk.x = *(uint32_t*)&h0;
            pk.y = *(uint32_t*)&h1;
            ((uint2*)g_wh)[i] = pk;
        }
        return;
    }

    // ---- gate for token t ----
    int t = blockIdx.x - CVT_BLOCKS;
    const float4* xr = x4 + (size_t)t * (DDIM / 4);
    uint2* xc = (uint2*)(g_xh + (size_t)t * DDIM);

    float acc[NE];
#pragma unroll
    for (int e = 0; e < NE; e++) acc[e] = 0.f;

    for (int i = threadIdx.x; i < DDIM / 4; i += 256) {
        float4 v = xr[i];
        __half2 h0 = __floats2half2_rn(v.x, v.y);
        __half2 h1 = __floats2half2_rn(v.z, v.w);
        uint2 pk;
        pk.x = *(uint32_t*)&h0;
        pk.y = *(uint32_t*)&h1;
        xc[i] = pk;
#pragma unroll
        for (int e = 0; e < NE; e++) {
            float4 w = gw1_4[e * (DDIM / 4) + i];
            acc[e] += v.x * w.x + v.y * w.y + v.z * w.z + v.w * w.w;
        }
    }
#pragma unroll
    for (int e = 0; e < NE; e++) {
#pragma unroll
        for (int o = 16; o > 0; o >>= 1)
            acc[e] += __shfl_xor_sync(0xffffffffu, acc[e], o);
    }
    __shared__ float part[NE][8];
    __shared__ float hs[NE];
    __shared__ float ls[NE];
    int lane = threadIdx.x & 31, warp = threadIdx.x >> 5;
    if (lane == 0) {
#pragma unroll
        for (int e = 0; e < NE; e++) part[e][warp] = acc[e];
    }
    __syncthreads();
    if (threadIdx.x < NE) {
        int e = threadIdx.x;
        float s = 0.f;
#pragma unroll
        for (int w = 0; w < 8; w++) s += part[e][w];
        hs[e] = tanhf(s);
    }
    __syncthreads();
    if (threadIdx.x < NE) {
        int j = threadIdx.x;
        float l = 0.f;
#pragma unroll
        for (int e = 0; e < NE; e++) l += gw2[j * NE + e] * hs[e];
        ls[j] = l;
    }
    __syncthreads();
    if (threadIdx.x == 0) {
        int i0 = 0; float v0 = ls[0];
        for (int j = 1; j < NE; j++) if (ls[j] > v0) { v0 = ls[j]; i0 = j; }
        int i1 = -1; float v1 = -3.4e38f;
        for (int j = 0; j < NE; j++) if (j != i0 && ls[j] > v1) { v1 = ls[j]; i1 = j; }
        float z  = expf(v1 - v0);
        float s0 = 1.f / (1.f + z);
        float s1 = z * s0;
        int p0 = atomicAdd(&g_cnt[i0], 1);
        g_tok[i0 * T_TOK + p0]   = t;
        g_scale[i0 * T_TOK + p0] = s0;
        int p1 = atomicAdd(&g_cnt[i1], 1);
        g_tok[i1 * T_TOK + p1]   = t;
        g_scale[i1 * T_TOK + p1] = s1;
        atomicAdd(&g_importance[i0], s0);
        atomicAdd(&g_importance[i1], s1);
    }
}

__global__ void loss_kernel(float* __restrict__ out) {
    float v[NE], w[NE];
    float m1 = 0.f, m2 = 0.f;
#pragma unroll
    for (int e = 0; e < NE; e++) {
        v[e] = g_importance[e];
        w[e] = (float)g_cnt[e];
        m1 += v[e]; m2 += w[e];
    }
    m1 *= (1.f / NE); m2 *= (1.f / NE);
    float var1 = 0.f, var2 = 0.f;
#pragma unroll
    for (int e = 0; e < NE; e++) {
        float d1 = v[e] - m1; var1 += d1 * d1;
        float d2 = w[e] - m2; var2 += d2 * d2;
    }
    var1 *= (1.f / (NE - 1)); var2 *= (1.f / (NE - 1));
    out[0] = 0.01f * (var1 / (m1 * m1 + 1e-10f) + var2 / (m2 * m2 + 1e-10f));
}

// ---------------------------------------------------------------
__device__ __forceinline__ void mma_f16(float* c, const uint32_t* a, const uint32_t* b) {
    asm volatile(
        "mma.sync.aligned.m16n8k16.row.col.f32.f16.f16.f32 "
        "{%0,%1,%2,%3}, {%4,%5,%6,%7}, {%8,%9}, {%0,%1,%2,%3};\n"
        : "+f"(c[0]), "+f"(c[1]), "+f"(c[2]), "+f"(c[3])
        : "r"(a[0]), "r"(a[1]), "r"(a[2]), "r"(a[3]), "r"(b[0]), "r"(b[1]));
}
__device__ __forceinline__ void ldm_x4(uint32_t& r0, uint32_t& r1, uint32_t& r2, uint32_t& r3,
                                       uint32_t saddr) {
    asm volatile("ldmatrix.sync.aligned.m8n8.x4.shared.b16 {%0,%1,%2,%3}, [%4];\n"
                 : "=r"(r0), "=r"(r1), "=r"(r2), "=r"(r3) : "r"(saddr));
}
__device__ __forceinline__ void cp_async16(uint32_t saddr, const void* gsrc) {
    asm volatile("cp.async.cg.shared.global [%0], [%1], 16;\n" :: "r"(saddr), "l"(gsrc) : "memory");
}

// Grouped expert GEMM on fp16 operands (fp32 accumulate); epilogue scatter-add.
// CTA tile 128x128, 4 warps, warp tile 64x64; ldmatrix fragment loads; BK=64.
// (R7 configuration — measured ~94% of legacy-HMMA pipe ceiling.)
__global__ void __launch_bounds__(GEMM_THREADS, 2)
moe_gemm(const float* __restrict__ bias, float* __restrict__ y) {
    int e   = blockIdx.z;
    int cnt = g_cnt[e];
    int m0  = blockIdx.x * BM;
    if (m0 >= cnt) return;
    int n0  = blockIdx.y * BN;

    extern __shared__ __half smh[];
    __half* Ash   = smh;                                   // NSTAGE*BM*ALD_H halves
    __half* Bsh   = Ash + NSTAGE * BM * ALD_H;             // NSTAGE*BN*ALD_H halves
    float* sBias  = (float*)(Bsh + NSTAGE * BN * ALD_H);   // BN
    float* sScale = sBias + BN;                            // BM
    int*   sTok   = (int*)(sScale + BM);                   // BM

    uint32_t sb = (uint32_t)__cvta_generic_to_shared(smh);
    uint32_t aStage0 = sb;
    uint32_t bStage0 = sb + NSTAGE * BM * ALD_H * 2;

    int tid = threadIdx.x;
    {
        int m = m0 + tid;
        bool valid = m < cnt;
        sTok[tid]   = valid ? g_tok[e * T_TOK + m]   : 0;
        sScale[tid] = valid ? g_scale[e * T_TOK + m] : 0.f;
        sBias[tid]  = bias[e * DDIM + n0 + tid];
    }
    __syncthreads();

    // cp.async slots: 128 threads cover 16 rows x 8 chunk-cols (16B=8 halves); 8 row-passes.
    int r_ld = tid >> 3, c_ld = tid & 7;     // r_ld 0..15, c_ld 0..7
    const __half* a_src[8];
#pragma unroll
    for (int it = 0; it < 8; it++) {
        int r = r_ld + it * 16;
        a_src[it] = g_xh + (size_t)sTok[r] * DDIM + c_ld * 8;
    }
    const __half* b_base = g_wh + ((size_t)e * DDIM + n0 + r_ld) * DDIM + c_ld * 8;
    uint32_t stDstA = aStage0 + (r_ld * ALD_H + c_ld * 8) * 2;
    uint32_t stDstB = bStage0 + (r_ld * ALD_H + c_ld * 8) * 2;

    auto load_stage = [&](int stage, int kt) {
        int kk = kt * BK;
        uint32_t so = (uint32_t)(stage * (BM * ALD_H * 2));
#pragma unroll
        for (int it = 0; it < 8; it++) {
            cp_async16(stDstA + so + it * (16 * ALD_H * 2), a_src[it] + kk);
        }
#pragma unroll
        for (int it = 0; it < 8; it++) {
            cp_async16(stDstB + so + it * (16 * ALD_H * 2),
                       b_base + (size_t)(it * 16) * DDIM + kk);
        }
        asm volatile("cp.async.commit_group;\n" ::: "memory");
    };

    const int KT = DDIM / BK;  // 64
    load_stage(0, 0);
    load_stage(1, 1);

    int warp = tid >> 5;        // 0..3
    int wm   = warp & 1;        // 2 warps along M -> 64 rows each
    int wn   = warp >> 1;       // 2 warps along N -> 64 cols each
    int lane = tid & 31;
    int gid  = lane >> 2;       // 0..7
    int tg   = lane & 3;        // 0..3

    // ldmatrix per-thread address components (halves)
    int rA = ((lane >> 3) & 1) * 8 + (lane & 7);   // row within 16-row A tile
    int cA = ((lane >> 4) & 1) * 8;                // k-chunk within k16
    int rB = ((lane >> 4) & 1) * 8 + (lane & 7);   // row within 16-row B (n) tile
    int cB = ((lane >> 3) & 1) * 8;

    float c[4][8][4];
#pragma unroll
    for (int mi = 0; mi < 4; mi++)
#pragma unroll
        for (int ni = 0; ni < 8; ni++)
#pragma unroll
            for (int j = 0; j < 4; j++) c[mi][ni][j] = 0.f;

    for (int i = 0; i < KT; i++) {
        if (i < KT - 1) {
            asm volatile("cp.async.wait_group 1;\n" ::: "memory");
        } else {
            asm volatile("cp.async.wait_group 0;\n" ::: "memory");
        }
        __syncthreads();
        if (i + 2 < KT) load_stage((i + 2) % NSTAGE, i + 2);

        uint32_t aBase = aStage0 + (i % NSTAGE) * (BM * ALD_H * 2)
                       + ((wm * 64 + rA) * ALD_H + cA) * 2;
        uint32_t bBase = bStage0 + (i % NSTAGE) * (BN * ALD_H * 2)
                       + ((wn * 64 + rB) * ALD_H + cB) * 2;

#pragma unroll
        for (int ks = 0; ks < BK / 16; ks++) {           // 4 k16 steps
            uint32_t a[4][4], b[8][2];
#pragma unroll
            for (int mi = 0; mi < 4; mi++) {
                ldm_x4(a[mi][0], a[mi][1], a[mi][2], a[mi][3],
                       aBase + (mi * 16 * ALD_H + ks * 16) * 2);
            }
#pragma unroll
            for (int p = 0; p < 4; p++) {                // ni pairs
                ldm_x4(b[2 * p][0], b[2 * p][1], b[2 * p + 1][0], b[2 * p + 1][1],
                       bBase + (p * 16 * ALD_H + ks * 16) * 2);
            }
#pragma unroll
            for (int mi = 0; mi < 4; mi++)
#pragma unroll
                for (int ni = 0; ni < 8; ni++)
                    mma_f16(c[mi][ni], a[mi], b[ni]);
        }
    }

    // epilogue: scatter-add
#pragma unroll
    for (int mi = 0; mi < 4; mi++) {
#pragma unroll
        for (int half = 0; half < 2; half++) {
            int r = wm * 64 + mi * 16 + gid + half * 8;
            if (m0 + r >= cnt) continue;
            int   tok = sTok[r];
            float sc  = sScale[r];
            float* yr = y + (size_t)tok * DDIM + n0;
#pragma unroll
            for (int ni = 0; ni < 8; ni++) {
                int col = wn * 64 + ni * 8 + tg * 2;
                float v0 = sc * (c[mi][ni][half * 2 + 0] + sBias[col]);
                float v1 = sc * (c[mi][ni][half * 2 + 1] + sBias[col + 1]);
                atomicAdd(&yr[col],     v0);
                atomicAdd(&yr[col + 1], v1);
            }
        }
    }
}

// ---------------------------------------------------------------
extern "C" void kernel_launch(void* const* d_in, const int* in_sizes, int n_in,
                              void* d_out, int out_size) {
    const float* x   = (const float*)d_in[0];
    const float* gw1 = (const float*)d_in[1];
    const float* gw2 = (const float*)d_in[2];
    const float* ew  = (const float*)d_in[3];
    const float* eb  = (const float*)d_in[4];
    float* out = (float*)d_out;

    // Launch order (5th launch incl. memset is the ncu-captured one -> moe_gemm):
    // memset(1), reset(2), prep(3), loss(4), moe_gemm(5).
    cudaMemsetAsync(out, 0, (size_t)out_size * sizeof(float));

    reset_kernel<<<1, 32>>>();

    prep_kernel<<<PREP_BLOCKS, 256>>>((const float4*)x, (const float4*)gw1, gw2,
                                      (const float4*)ew);

    if (out_size > T_TOK * DDIM) {
        loss_kernel<<<1, 1>>>(out + (size_t)T_TOK * DDIM);
    }

    int smem_bytes = (NSTAGE * (BM * ALD_H + BN * ALD_H)) * 2 + (BN + BM + BM) * 4;
    cudaFuncSetAttribute(moe_gemm, cudaFuncAttributeMaxDynamicSharedMemorySize, smem_bytes);
    moe_gemm<<<dim3(T_TOK / BM, DDIM / BN, NE), GEMM_THREADS, smem_bytes>>>(eb, out);
}